// round 15
// baseline (speedup 1.0000x reference)
#include <cuda_runtime.h>
#include <cuda_bf16.h>

#define NBOUND 19            // NUM_BINS - 1 boundaries per code
#define NBINS  20
#define ED     768
#define V4     192           // float4 per row
#define COLS_PER_LANE 6      // 192 / 32
#define WARPS_PER_CTA 8
#define TPB   (32 * WARPS_PER_CTA)   // 256

__global__ __launch_bounds__(TPB) void sde_kernel(
    const float* __restrict__ values,
    const int*   __restrict__ code_ids,
    const float* __restrict__ boundaries,
    const float4* __restrict__ embed,
    float4* __restrict__ out,
    int batch)
{
    const int lane = threadIdx.x & 31;
    const int wid  = threadIdx.x >> 5;
    const int row  = blockIdx.x * WARPS_PER_CTA + wid;
    if (row >= batch) return;

    // ---- per-row scalars, computed once per warp, fully uniform ----
    const float v    = __ldg(values + row);       // broadcast load
    const int   code = __ldg(code_ids + row);     // broadcast load
    float bj = 3.0e38f;
    if (lane < NBOUND) bj = __ldg(boundaries + (size_t)code * NBOUND + lane);

    // searchsorted (side='left'): idx = count of boundaries strictly < v
    const unsigned m = __ballot_sync(0xffffffffu, bj < v);
    const int idx = __popc(m);                    // in [0, 19], uniform

    const int lo_i = min(max(idx - 1, 0), NBOUND - 1);
    const int hi_i = min(idx, NBOUND - 1);
    const float lo_b = __shfl_sync(0xffffffffu, bj, lo_i);  // uniform
    const float hi_b = __shfl_sync(0xffffffffu, bj, hi_i);  // uniform

    const bool interior = (idx > 0) && (idx < NBINS - 1);
    const int lower = (idx == 0) ? 0 : ((idx >= NBINS - 1) ? (NBINS - 1) : idx - 1);
    float4* out_row = out + (size_t)row * V4;

    if (!interior) {
        // warp-uniform fast path (~10% of rows): alpha==0, upper==lower,
        // output is a pure copy of one table row — half the loads, no FMA.
        const float4* lo_row = embed + (size_t)lower * V4;
#pragma unroll
        for (int j = 0; j < COLS_PER_LANE; j++) {
            const int col = j * 32 + lane;
            __stwt(out_row + col, __ldg(lo_row + col));
        }
        return;
    }

    const float denom = hi_b - lo_b;
    float a;
    if (fabsf(denom) < 1e-8f) {
        a = 0.5f;
    } else {
        a = fminf(fmaxf((v - lo_b) / denom, 0.0f), 1.0f);
    }
    const float na = 1.0f - a;
    const int upper = idx;   // interior => upper = idx, lower = idx-1

    // ---- streaming phase: 6 float4 columns per lane ----
    // Loads hit the L1-resident 61KB table; stores are the mandatory
    // 403MB DRAM traffic. __stwt (write-through) drains stores toward
    // DRAM without L2 dirty-line allocation/eviction bookkeeping.
    const float4* lo_row = embed + (size_t)lower * V4;
    const float4* up_row = embed + (size_t)upper * V4;

#pragma unroll
    for (int j = 0; j < COLS_PER_LANE; j++) {
        const int col = j * 32 + lane;
        const float4 l4 = __ldg(lo_row + col);
        const float4 u4 = __ldg(up_row + col);
        float4 o;
        o.x = na * l4.x + a * u4.x;
        o.y = na * l4.y + a * u4.y;
        o.z = na * l4.z + a * u4.z;
        o.w = na * l4.w + a * u4.w;
        __stwt(out_row + col, o);
    }
}

extern "C" void kernel_launch(void* const* d_in, const int* in_sizes, int n_in,
                              void* d_out, int out_size) {
    const float*  values     = (const float*)d_in[0];
    const int*    code_ids   = (const int*)d_in[1];
    const float*  boundaries = (const float*)d_in[2];
    const float4* embed      = (const float4*)d_in[3];
    float4* out = (float4*)d_out;

    const int batch = in_sizes[0];   // 131072 rows
    const int grid  = (batch + WARPS_PER_CTA - 1) / WARPS_PER_CTA;
    sde_kernel<<<grid, TPB>>>(values, code_ids, boundaries, embed, out, batch);
}

// round 17
// speedup vs baseline: 1.0432x; 1.0432x over previous
#include <cuda_runtime.h>
#include <cuda_bf16.h>

#define NBOUND 19            // NUM_BINS - 1 boundaries per code
#define NBINS  20
#define ED     768
#define V4     192           // float4 per row
#define COLS_PER_LANE 6      // 192 / 32
#define WARPS_PER_CTA 8
#define TPB   (32 * WARPS_PER_CTA)   // 256

__global__ __launch_bounds__(TPB) void sde_kernel(
    const float* __restrict__ values,
    const int*   __restrict__ code_ids,
    const float* __restrict__ boundaries,
    const float4* __restrict__ embed,
    float4* __restrict__ out,
    int batch)
{
    const int lane = threadIdx.x & 31;
    const int wid  = threadIdx.x >> 5;
    const int row  = blockIdx.x * WARPS_PER_CTA + wid;
    if (row >= batch) return;

    // ---- per-row scalars, computed once per warp, fully uniform ----
    const float v    = __ldg(values + row);       // broadcast load
    const int   code = __ldg(code_ids + row);     // broadcast load
    float bj = 3.0e38f;
    if (lane < NBOUND) bj = __ldg(boundaries + (size_t)code * NBOUND + lane);

    // searchsorted (side='left'): idx = count of boundaries strictly < v
    const unsigned m = __ballot_sync(0xffffffffu, bj < v);
    const int idx = __popc(m);                    // in [0, 19], uniform

    const int lo_i = min(max(idx - 1, 0), NBOUND - 1);
    const int hi_i = min(idx, NBOUND - 1);
    const float lo_b = __shfl_sync(0xffffffffu, bj, lo_i);  // uniform
    const float hi_b = __shfl_sync(0xffffffffu, bj, hi_i);  // uniform

    const bool interior = (idx > 0) && (idx < NBINS - 1);
    const float denom = hi_b - lo_b;
    float a;
    if (fabsf(denom) < 1e-8f) {
        a = 0.5f;
    } else {
        a = fminf(fmaxf((v - lo_b) / denom, 0.0f), 1.0f);
    }
    if (!interior) a = 0.0f;
    const float na = 1.0f - a;

    const int lower = (idx == 0) ? 0 : ((idx >= NBINS - 1) ? (NBINS - 1) : idx - 1);
    const int upper = interior ? idx : lower;

    // ---- streaming phase: 6 float4 columns per lane ----
    // Loads hit the L1-resident 61KB table; stores are the mandatory
    // 403MB DRAM traffic. __stcs marks output stream-once (evict-first)
    // so the write data doesn't churn L2 allocation — measured best
    // policy (beats default STG by ~1.8us and .wt by ~2.2us).
    const float4* lo_row = embed + (size_t)lower * V4;
    const float4* up_row = embed + (size_t)upper * V4;
    float4* out_row = out + (size_t)row * V4;

#pragma unroll
    for (int j = 0; j < COLS_PER_LANE; j++) {
        const int col = j * 32 + lane;
        const float4 l4 = __ldg(lo_row + col);
        const float4 u4 = __ldg(up_row + col);
        float4 o;
        o.x = na * l4.x + a * u4.x;
        o.y = na * l4.y + a * u4.y;
        o.z = na * l4.z + a * u4.z;
        o.w = na * l4.w + a * u4.w;
        __stcs(out_row + col, o);
    }
}

extern "C" void kernel_launch(void* const* d_in, const int* in_sizes, int n_in,
                              void* d_out, int out_size) {
    const float*  values     = (const float*)d_in[0];
    const int*    code_ids   = (const int*)d_in[1];
    const float*  boundaries = (const float*)d_in[2];
    const float4* embed      = (const float4*)d_in[3];
    float4* out = (float4*)d_out;

    const int batch = in_sizes[0];   // 131072 rows
    const int grid  = (batch + WARPS_PER_CTA - 1) / WARPS_PER_CTA;
    sde_kernel<<<grid, TPB>>>(values, code_ids, boundaries, embed, out, batch);
}